// round 4
// baseline (speedup 1.0000x reference)
#include <cuda_runtime.h>
#include <math.h>

#define BATCH   32
#define NSRC    4
#define TLEN    64000
#define T4      (TLEN / 4)      // 16000 float4 per stream per batch
#define CHUNKS  32              // blocks per batch
#define PER_BLK (T4 / CHUNKS)   // 500 float4 per block per stream
#define NSTAT   20
#define NPAIR   (BATCH * NSTAT) // 640
#define NK      16
#define THREADS 256
#define NBLOCKS (BATCH * CHUNKS)

// Transposed partials: [pair][chunk], pair = b*NSTAT + st. Chunk values are
// contiguous -> the final reduce is 8x float4 per pair (MLP 8).
__device__ float g_partials[NPAIR * CHUNKS];
__device__ int   g_count = 0;   // arrival counter, reset by the last block

// stat layout:
//  0..9  : Gram upper triangle (0,0)(0,1)(0,2)(0,3)(1,1)(1,2)(1,3)(2,2)(2,3)(3,3)
// 10..13 : P1[s] = sum e_s * m1
// 14..17 : P2[s] = sum e_s * m2
// 18     : ||m1||^2   19 : ||m2||^2

__device__ __forceinline__ float sum4(float4 v) {
    return (v.x + v.y) + (v.z + v.w);
}

__device__ __forceinline__ float mixit_loss(int k, const float* __restrict__ st)
{
    // st points to the 20 stats of batch b (shared memory)
    float m[NSRC], mc[NSRC];
#pragma unroll
    for (int s = 0; s < NSRC; s++) {
        m[s]  = (float)((k >> (3 - s)) & 1);   // itertools.product: last varies fastest
        mc[s] = 1.0f - m[s];
    }
    const int gi[4][4] = {{0,1,2,3},{1,4,5,6},{2,5,7,8},{3,6,8,9}};

    float q0 = 0.0f, q1 = 0.0f, c0 = 0.0f, c1 = 0.0f;
#pragma unroll
    for (int s = 0; s < NSRC; s++) {
#pragma unroll
        for (int s2 = 0; s2 < NSRC; s2++) {
            float g = st[gi[s][s2]];
            q0 = fmaf(m[s]  * m[s2],  g, q0);
            q1 = fmaf(mc[s] * mc[s2], g, q1);
        }
        c0 = fmaf(m[s],  st[10 + s], c0);
        c1 = fmaf(mc[s], st[14 + s], c1);
    }
    const float a0 = q0 - 2.0f * c0 + st[18];   // ||mix0 - m1||^2
    const float a1 = q1 - 2.0f * c1 + st[19];   // ||mix1 - m2||^2

    return 10.0f * (__log10f(fmaf(30.0f, q0, a0)) - __log10f(q0)) +
           10.0f * (__log10f(fmaf(30.0f, q1, a1)) - __log10f(q1));
}

__global__ __launch_bounds__(THREADS)
void mixit_kernel(const float* __restrict__ est,
                  const float* __restrict__ m1,
                  const float* __restrict__ m2,
                  float* __restrict__ out, int out_size)
{
    const int blk   = blockIdx.x;          // b * CHUNKS + chunk
    const int b     = blk / CHUNKS;
    const int chunk = blk % CHUNKS;
    const int start = chunk * PER_BLK;
    const int end   = start + PER_BLK;

    const float4* e0 = (const float4*)(est + (size_t)b * NSRC * TLEN + 0 * (size_t)TLEN);
    const float4* e1 = (const float4*)(est + (size_t)b * NSRC * TLEN + 1 * (size_t)TLEN);
    const float4* e2 = (const float4*)(est + (size_t)b * NSRC * TLEN + 2 * (size_t)TLEN);
    const float4* e3 = (const float4*)(est + (size_t)b * NSRC * TLEN + 3 * (size_t)TLEN);
    const float4* p1 = (const float4*)(m1 + (size_t)b * TLEN);
    const float4* p2 = (const float4*)(m2 + (size_t)b * TLEN);

    float acc[NSTAT];
#pragma unroll
    for (int i = 0; i < NSTAT; i++) acc[i] = 0.0f;

    for (int i = start + threadIdx.x; i < end; i += THREADS) {
        float4 a0 = e0[i], a1 = e1[i], a2 = e2[i], a3 = e3[i];
        float4 v1 = p1[i], v2 = p2[i];

#define LANE(C) do {                                                       \
        float x0 = a0.C, x1 = a1.C, x2 = a2.C, x3 = a3.C;                  \
        float y1 = v1.C, y2 = v2.C;                                        \
        acc[0]  = fmaf(x0, x0, acc[0]);                                    \
        acc[1]  = fmaf(x0, x1, acc[1]);                                    \
        acc[2]  = fmaf(x0, x2, acc[2]);                                    \
        acc[3]  = fmaf(x0, x3, acc[3]);                                    \
        acc[4]  = fmaf(x1, x1, acc[4]);                                    \
        acc[5]  = fmaf(x1, x2, acc[5]);                                    \
        acc[6]  = fmaf(x1, x3, acc[6]);                                    \
        acc[7]  = fmaf(x2, x2, acc[7]);                                    \
        acc[8]  = fmaf(x2, x3, acc[8]);                                    \
        acc[9]  = fmaf(x3, x3, acc[9]);                                    \
        acc[10] = fmaf(x0, y1, acc[10]);                                   \
        acc[11] = fmaf(x1, y1, acc[11]);                                   \
        acc[12] = fmaf(x2, y1, acc[12]);                                   \
        acc[13] = fmaf(x3, y1, acc[13]);                                   \
        acc[14] = fmaf(x0, y2, acc[14]);                                   \
        acc[15] = fmaf(x1, y2, acc[15]);                                   \
        acc[16] = fmaf(x2, y2, acc[16]);                                   \
        acc[17] = fmaf(x3, y2, acc[17]);                                   \
        acc[18] = fmaf(y1, y1, acc[18]);                                   \
        acc[19] = fmaf(y2, y2, acc[19]);                                   \
    } while (0)

        LANE(x); LANE(y); LANE(z); LANE(w);
#undef LANE
    }

    // warp reduce each stat
#pragma unroll
    for (int st = 0; st < NSTAT; st++) {
        float v = acc[st];
        v += __shfl_down_sync(0xffffffffu, v, 16);
        v += __shfl_down_sync(0xffffffffu, v, 8);
        v += __shfl_down_sync(0xffffffffu, v, 4);
        v += __shfl_down_sync(0xffffffffu, v, 2);
        v += __shfl_down_sync(0xffffffffu, v, 1);
        acc[st] = v;
    }

    __shared__ float sred[THREADS / 32][NSTAT];
    const int warp = threadIdx.x >> 5;
    const int lane = threadIdx.x & 31;
    if (lane == 0) {
#pragma unroll
        for (int st = 0; st < NSTAT; st++) sred[warp][st] = acc[st];
    }
    __syncthreads();

    if (threadIdx.x < NSTAT) {
        float s = 0.0f;
#pragma unroll
        for (int w = 0; w < THREADS / 32; w++) s += sred[w][threadIdx.x];
        // transposed: [pair][chunk]
        g_partials[(b * NSTAT + threadIdx.x) * CHUNKS + chunk] = s;
    }

    // ---- last-block epilogue -------------------------------------------
    __shared__ int s_last;
    __threadfence();                    // make partials visible
    if (threadIdx.x == 0) {
        int old = atomicAdd(&g_count, 1);
        s_last = (old == NBLOCKS - 1) ? 1 : 0;
    }
    __syncthreads();
    if (!s_last) return;
    __threadfence();                    // acquire side

    __shared__ float sstats[NPAIR];     // [b][st] flattened: 2.5 KB
    __shared__ float ksum[NK];

    // Phase 1: reduce chunks. 640 pairs / 256 threads = 3 rounds, 8x float4 each.
    for (int p = threadIdx.x; p < NPAIR; p += THREADS) {
        const float4* row = (const float4*)(g_partials + p * CHUNKS);
        float4 r0 = row[0], r1 = row[1], r2 = row[2], r3 = row[3];
        float4 r4 = row[4], r5 = row[5], r6 = row[6], r7 = row[7];
        float s01 = sum4(r0) + sum4(r1);
        float s23 = sum4(r2) + sum4(r3);
        float s45 = sum4(r4) + sum4(r5);
        float s67 = sum4(r6) + sum4(r7);
        sstats[p] = (s01 + s23) + (s45 + s67);
    }
    __syncthreads();

    // Phase 2: 8 warps; warp w, lane = batch index. Each warp does k=w and k=w+8.
    {
        const int w  = threadIdx.x >> 5;
        const int bb = threadIdx.x & 31;
        const float* st = &sstats[bb * NSTAT];

        float l0 = mixit_loss(w,     st);
        float l1 = mixit_loss(w + 8, st);
#pragma unroll
        for (int off = 16; off > 0; off >>= 1) {
            l0 += __shfl_down_sync(0xffffffffu, l0, off);
            l1 += __shfl_down_sync(0xffffffffu, l1, off);
        }
        if (bb == 0) { ksum[w] = l0; ksum[w + 8] = l1; }
    }
    __syncthreads();

    if (threadIdx.x == 0) {
        float best = ksum[0];
        int bi = 0;
#pragma unroll
        for (int kk = 1; kk < NK; kk++) {
            float v = ksum[kk];
            if (v < best) { best = v; bi = kk; }   // first occurrence wins (jnp.argmin)
        }
        out[0] = (float)bi;
        if (out_size > 1) out[1] = best;
        g_count = 0;                     // reset for next replay
    }
}

extern "C" void kernel_launch(void* const* d_in, const int* in_sizes, int n_in,
                              void* d_out, int out_size)
{
    const float* est = (const float*)d_in[0];   // [32, 4, 64000]
    const float* m1  = (const float*)d_in[1];   // [32, 64000]
    const float* m2  = (const float*)d_in[2];   // [32, 64000]

    mixit_kernel<<<NBLOCKS, THREADS>>>(est, m1, m2, (float*)d_out, out_size);
}

// round 5
// speedup vs baseline: 1.1356x; 1.1356x over previous
#include <cuda_runtime.h>
#include <math.h>
#include <stdint.h>

#define BATCH    32
#define NSRC     4
#define TLEN     64000
#define NSTAT    20
#define NPAIR    (BATCH * NSTAT)    // 640
#define NK       16
#define THREADS  256
#define CPB      4                  // chunks (blocks) per batch
#define NBLOCKS  (BATCH * CPB)      // 128
#define QCHUNK   (TLEN / CPB)       // 16000 floats per block per stream

#define NSTAGES     3
#define TILE_FLOATS 2000
#define TILE_F4     (TILE_FLOATS / 4)       // 500
#define TILE_B      (TILE_FLOATS * 4)       // 8000 bytes
#define STREAMS     6
#define STAGE_B     (TILE_B * STREAMS)      // 48000 bytes
#define NTILES      (QCHUNK / TILE_FLOATS)  // 8

// smem layout: [0..24) full mbarriers (3x8), [64..88) empty mbarriers, data at 1024
#define SM_FULL(s)  (s * 8)
#define SM_EMPTY(s) (64 + s * 8)
#define SM_DATA     1024
#define SMEM_TOTAL  (SM_DATA + NSTAGES * STAGE_B)   // 145024

// Partials: [pair][chunk], pair = b*NSTAT+st, 4 chunks -> one float4 per pair.
__device__ float g_partials[NPAIR * CPB];
__device__ int   g_count = 0;

__device__ __forceinline__ uint32_t smem_u32(const void* p) {
    uint32_t a;
    asm("{ .reg .u64 t; cvta.to.shared.u64 t, %1; cvt.u32.u64 %0, t; }" : "=r"(a) : "l"(p));
    return a;
}
__device__ __forceinline__ void mbar_init(uint32_t m, uint32_t cnt) {
    asm volatile("mbarrier.init.shared.b64 [%0], %1;" :: "r"(m), "r"(cnt) : "memory");
}
__device__ __forceinline__ void mbar_arrive(uint32_t m) {
    asm volatile("mbarrier.arrive.shared.b64 _, [%0];" :: "r"(m) : "memory");
}
__device__ __forceinline__ void mbar_expect_tx(uint32_t m, uint32_t bytes) {
    asm volatile("mbarrier.arrive.expect_tx.shared.b64 _, [%0], %1;" :: "r"(m), "r"(bytes) : "memory");
}
__device__ __forceinline__ void mbar_wait(uint32_t m, uint32_t parity) {
    asm volatile(
        "{\n\t.reg .pred P;\n\t"
        "W_%=:\n\t"
        "mbarrier.try_wait.parity.acquire.cta.shared::cta.b64 P, [%0], %1, 0x989680;\n\t"
        "@P bra D_%=;\n\t"
        "bra W_%=;\n\t"
        "D_%=:\n\t}"
        :: "r"(m), "r"(parity) : "memory");
}
__device__ __forceinline__ void bulk_g2s(uint32_t dst, const void* src, uint32_t bytes, uint32_t mbar) {
    asm volatile(
        "cp.async.bulk.shared::cluster.global.mbarrier::complete_tx::bytes [%0], [%1], %2, [%3];"
        :: "r"(dst), "l"(src), "r"(bytes), "r"(mbar) : "memory");
}

__device__ __forceinline__ float sum4(float4 v) { return (v.x + v.y) + (v.z + v.w); }

// stat layout: 0..9 Gram UT (00,01,02,03,11,12,13,22,23,33); 10..13 P1; 14..17 P2; 18 |m1|^2; 19 |m2|^2
__device__ __forceinline__ float mixit_loss(int k, const float* __restrict__ st)
{
    float m[NSRC], mc[NSRC];
#pragma unroll
    for (int s = 0; s < NSRC; s++) {
        m[s]  = (float)((k >> (3 - s)) & 1);   // itertools.product: last varies fastest
        mc[s] = 1.0f - m[s];
    }
    const int gi[4][4] = {{0,1,2,3},{1,4,5,6},{2,5,7,8},{3,6,8,9}};
    float q0 = 0.0f, q1 = 0.0f, c0 = 0.0f, c1 = 0.0f;
#pragma unroll
    for (int s = 0; s < NSRC; s++) {
#pragma unroll
        for (int s2 = 0; s2 < NSRC; s2++) {
            float g = st[gi[s][s2]];
            q0 = fmaf(m[s]  * m[s2],  g, q0);
            q1 = fmaf(mc[s] * mc[s2], g, q1);
        }
        c0 = fmaf(m[s],  st[10 + s], c0);
        c1 = fmaf(mc[s], st[14 + s], c1);
    }
    const float a0 = q0 - 2.0f * c0 + st[18];
    const float a1 = q1 - 2.0f * c1 + st[19];
    return 10.0f * (__log10f(fmaf(30.0f, q0, a0)) - __log10f(q0)) +
           10.0f * (__log10f(fmaf(30.0f, q1, a1)) - __log10f(q1));
}

__global__ __launch_bounds__(THREADS)
void mixit_kernel(const float* __restrict__ est,
                  const float* __restrict__ m1,
                  const float* __restrict__ m2,
                  float* __restrict__ out, int out_size)
{
    extern __shared__ char smem[];
    const uint32_t sb  = smem_u32(smem);
    const int tid = threadIdx.x;
    const int blk = blockIdx.x;           // b * CPB + q
    const int b   = blk / CPB;
    const int q   = blk % CPB;

    // 6 source streams for this block's quarter of batch b
    const float* srcs[STREAMS];
#pragma unroll
    for (int s = 0; s < NSRC; s++)
        srcs[s] = est + (size_t)b * NSRC * TLEN + (size_t)s * TLEN + (size_t)q * QCHUNK;
    srcs[4] = m1 + (size_t)b * TLEN + (size_t)q * QCHUNK;
    srcs[5] = m2 + (size_t)b * TLEN + (size_t)q * QCHUNK;

    if (tid == 0) {
#pragma unroll
        for (int s = 0; s < NSTAGES; s++) {
            mbar_init(sb + SM_FULL(s), 1);
            mbar_init(sb + SM_EMPTY(s), THREADS);
        }
    }
    __syncthreads();

    // prologue: issue first NSTAGES tiles (no empty-wait on first use)
    if (tid == 0) {
#pragma unroll
        for (int t = 0; t < NSTAGES; t++) {
            const uint32_t mb = sb + SM_FULL(t);
            mbar_expect_tx(mb, STAGE_B);
#pragma unroll
            for (int j = 0; j < STREAMS; j++)
                bulk_g2s(sb + SM_DATA + t * STAGE_B + j * TILE_B,
                         srcs[j] + (size_t)t * TILE_FLOATS, TILE_B, mb);
        }
    }

    float acc[NSTAT];
#pragma unroll
    for (int i = 0; i < NSTAT; i++) acc[i] = 0.0f;

    for (int t = 0; t < NTILES; t++) {
        const int stage = t % NSTAGES;
        const int use   = t / NSTAGES;
        mbar_wait(sb + SM_FULL(stage), use & 1);

        const char* base = smem + SM_DATA + stage * STAGE_B;
        const float4* e0 = (const float4*)(base + 0 * TILE_B);
        const float4* e1 = (const float4*)(base + 1 * TILE_B);
        const float4* e2 = (const float4*)(base + 2 * TILE_B);
        const float4* e3 = (const float4*)(base + 3 * TILE_B);
        const float4* p1 = (const float4*)(base + 4 * TILE_B);
        const float4* p2 = (const float4*)(base + 5 * TILE_B);

        for (int i = tid; i < TILE_F4; i += THREADS) {
            float4 a0 = e0[i], a1 = e1[i], a2 = e2[i], a3 = e3[i];
            float4 v1 = p1[i], v2 = p2[i];

#define LANE(C) do {                                                       \
            float x0 = a0.C, x1 = a1.C, x2 = a2.C, x3 = a3.C;              \
            float y1 = v1.C, y2 = v2.C;                                    \
            acc[0]  = fmaf(x0, x0, acc[0]);                                \
            acc[1]  = fmaf(x0, x1, acc[1]);                                \
            acc[2]  = fmaf(x0, x2, acc[2]);                                \
            acc[3]  = fmaf(x0, x3, acc[3]);                                \
            acc[4]  = fmaf(x1, x1, acc[4]);                                \
            acc[5]  = fmaf(x1, x2, acc[5]);                                \
            acc[6]  = fmaf(x1, x3, acc[6]);                                \
            acc[7]  = fmaf(x2, x2, acc[7]);                                \
            acc[8]  = fmaf(x2, x3, acc[8]);                                \
            acc[9]  = fmaf(x3, x3, acc[9]);                                \
            acc[10] = fmaf(x0, y1, acc[10]);                               \
            acc[11] = fmaf(x1, y1, acc[11]);                               \
            acc[12] = fmaf(x2, y1, acc[12]);                               \
            acc[13] = fmaf(x3, y1, acc[13]);                               \
            acc[14] = fmaf(x0, y2, acc[14]);                               \
            acc[15] = fmaf(x1, y2, acc[15]);                               \
            acc[16] = fmaf(x2, y2, acc[16]);                               \
            acc[17] = fmaf(x3, y2, acc[17]);                               \
            acc[18] = fmaf(y1, y1, acc[18]);                               \
            acc[19] = fmaf(y2, y2, acc[19]);                               \
        } while (0)

            LANE(x); LANE(y); LANE(z); LANE(w);
#undef LANE
        }

        mbar_arrive(sb + SM_EMPTY(stage));

        // producer: refill this stage for tile t+NSTAGES
        if (tid == 0 && t + NSTAGES < NTILES) {
            const int t2 = t + NSTAGES;               // same stage
            mbar_wait(sb + SM_EMPTY(stage), (t2 / NSTAGES - 1) & 1);
            const uint32_t mb = sb + SM_FULL(stage);
            mbar_expect_tx(mb, STAGE_B);
#pragma unroll
            for (int j = 0; j < STREAMS; j++)
                bulk_g2s(sb + SM_DATA + stage * STAGE_B + j * TILE_B,
                         srcs[j] + (size_t)t2 * TILE_FLOATS, TILE_B, mb);
        }
    }

    // block reduction of the 20 stats
#pragma unroll
    for (int st = 0; st < NSTAT; st++) {
        float v = acc[st];
        v += __shfl_down_sync(0xffffffffu, v, 16);
        v += __shfl_down_sync(0xffffffffu, v, 8);
        v += __shfl_down_sync(0xffffffffu, v, 4);
        v += __shfl_down_sync(0xffffffffu, v, 2);
        v += __shfl_down_sync(0xffffffffu, v, 1);
        acc[st] = v;
    }
    __shared__ float sred[THREADS / 32][NSTAT];
    const int warp = tid >> 5;
    const int lane = tid & 31;
    if (lane == 0) {
#pragma unroll
        for (int st = 0; st < NSTAT; st++) sred[warp][st] = acc[st];
    }
    __syncthreads();
    if (tid < NSTAT) {
        float s = 0.0f;
#pragma unroll
        for (int w = 0; w < THREADS / 32; w++) s += sred[w][tid];
        g_partials[(b * NSTAT + tid) * CPB + q] = s;
    }

    // ---- last-block epilogue -------------------------------------------
    __shared__ int s_last;
    __threadfence();
    if (tid == 0) {
        int old = atomicAdd(&g_count, 1);
        s_last = (old == NBLOCKS - 1) ? 1 : 0;
    }
    __syncthreads();
    if (!s_last) return;
    __threadfence();

    __shared__ float sstats[NPAIR];
    __shared__ float ksum[NK];

    for (int p = tid; p < NPAIR; p += THREADS) {
        float4 r = ((const float4*)g_partials)[p];
        sstats[p] = sum4(r);
    }
    __syncthreads();

    {
        const int w  = tid >> 5;
        const int bb = tid & 31;
        const float* st = &sstats[bb * NSTAT];
        float l0 = mixit_loss(w,     st);
        float l1 = mixit_loss(w + 8, st);
#pragma unroll
        for (int off = 16; off > 0; off >>= 1) {
            l0 += __shfl_down_sync(0xffffffffu, l0, off);
            l1 += __shfl_down_sync(0xffffffffu, l1, off);
        }
        if (bb == 0) { ksum[w] = l0; ksum[w + 8] = l1; }
    }
    __syncthreads();

    if (tid == 0) {
        float best = ksum[0];
        int bi = 0;
#pragma unroll
        for (int kk = 1; kk < NK; kk++) {
            float v = ksum[kk];
            if (v < best) { best = v; bi = kk; }   // first occurrence wins (jnp.argmin)
        }
        out[0] = (float)bi;
        if (out_size > 1) out[1] = best;
        g_count = 0;
    }
}

extern "C" void kernel_launch(void* const* d_in, const int* in_sizes, int n_in,
                              void* d_out, int out_size)
{
    const float* est = (const float*)d_in[0];   // [32, 4, 64000]
    const float* m1  = (const float*)d_in[1];   // [32, 64000]
    const float* m2  = (const float*)d_in[2];   // [32, 64000]

    cudaFuncSetAttribute(mixit_kernel, cudaFuncAttributeMaxDynamicSharedMemorySize, SMEM_TOTAL);
    mixit_kernel<<<NBLOCKS, THREADS, SMEM_TOTAL>>>(est, m1, m2, (float*)d_out, out_size);
}

// round 6
// speedup vs baseline: 1.3400x; 1.1800x over previous
#include <cuda_runtime.h>
#include <math.h>

#define BATCH    32
#define NSRC     4
#define TLEN     64000
#define NSTAT    20
#define NPAIR    (BATCH * NSTAT)    // 640
#define NK       16
#define THREADS  256
#define CPB      16                 // chunks (blocks) per batch
#define NBLOCKS  (BATCH * CPB)      // 512 = one full wave at 4 CTA/SM
#define QF4      (TLEN / 4 / CPB)   // 1000 float4 per block per stream

// Partials: [pair][chunk], pair = b*NSTAT+st, 16 chunks -> 4 float4 per pair.
__device__ float g_partials[NPAIR * CPB];
__device__ int   g_count = 0;

__device__ __forceinline__ float sum4(float4 v) { return (v.x + v.y) + (v.z + v.w); }

// stat layout: 0..9 Gram UT (00,01,02,03,11,12,13,22,23,33); 10..13 P1; 14..17 P2; 18 |m1|^2; 19 |m2|^2
__device__ __forceinline__ float mixit_loss(int k, const float* __restrict__ st)
{
    float m[NSRC], mc[NSRC];
#pragma unroll
    for (int s = 0; s < NSRC; s++) {
        m[s]  = (float)((k >> (3 - s)) & 1);   // itertools.product: last varies fastest
        mc[s] = 1.0f - m[s];
    }
    const int gi[4][4] = {{0,1,2,3},{1,4,5,6},{2,5,7,8},{3,6,8,9}};
    float q0 = 0.0f, q1 = 0.0f, c0 = 0.0f, c1 = 0.0f;
#pragma unroll
    for (int s = 0; s < NSRC; s++) {
#pragma unroll
        for (int s2 = 0; s2 < NSRC; s2++) {
            float g = st[gi[s][s2]];
            q0 = fmaf(m[s]  * m[s2],  g, q0);
            q1 = fmaf(mc[s] * mc[s2], g, q1);
        }
        c0 = fmaf(m[s],  st[10 + s], c0);
        c1 = fmaf(mc[s], st[14 + s], c1);
    }
    const float a0 = q0 - 2.0f * c0 + st[18];
    const float a1 = q1 - 2.0f * c1 + st[19];
    return 10.0f * (__log10f(fmaf(30.0f, q0, a0)) - __log10f(q0)) +
           10.0f * (__log10f(fmaf(30.0f, q1, a1)) - __log10f(q1));
}

__global__ __launch_bounds__(THREADS, 4)
void mixit_kernel(const float* __restrict__ est,
                  const float* __restrict__ m1,
                  const float* __restrict__ m2,
                  float* __restrict__ out, int out_size)
{
    const int tid = threadIdx.x;
    const int blk = blockIdx.x;            // b * CPB + q
    const int b   = blk / CPB;
    const int q   = blk % CPB;

    const float4* e0 = (const float4*)(est + (size_t)b * NSRC * TLEN + 0 * (size_t)TLEN) + (size_t)q * QF4;
    const float4* e1 = (const float4*)(est + (size_t)b * NSRC * TLEN + 1 * (size_t)TLEN) + (size_t)q * QF4;
    const float4* e2 = (const float4*)(est + (size_t)b * NSRC * TLEN + 2 * (size_t)TLEN) + (size_t)q * QF4;
    const float4* e3 = (const float4*)(est + (size_t)b * NSRC * TLEN + 3 * (size_t)TLEN) + (size_t)q * QF4;
    const float4* p1 = (const float4*)(m1 + (size_t)b * TLEN) + (size_t)q * QF4;
    const float4* p2 = (const float4*)(m2 + (size_t)b * TLEN) + (size_t)q * QF4;

    float acc[NSTAT];
#pragma unroll
    for (int i = 0; i < NSTAT; i++) acc[i] = 0.0f;

#pragma unroll 2
    for (int i = tid; i < QF4; i += THREADS) {
        float4 a0 = __ldcs(e0 + i);
        float4 a1 = __ldcs(e1 + i);
        float4 a2 = __ldcs(e2 + i);
        float4 a3 = __ldcs(e3 + i);
        float4 v1 = __ldcs(p1 + i);
        float4 v2 = __ldcs(p2 + i);

#define LANE(C) do {                                                       \
        float x0 = a0.C, x1 = a1.C, x2 = a2.C, x3 = a3.C;                  \
        float y1 = v1.C, y2 = v2.C;                                        \
        acc[0]  = fmaf(x0, x0, acc[0]);                                    \
        acc[1]  = fmaf(x0, x1, acc[1]);                                    \
        acc[2]  = fmaf(x0, x2, acc[2]);                                    \
        acc[3]  = fmaf(x0, x3, acc[3]);                                    \
        acc[4]  = fmaf(x1, x1, acc[4]);                                    \
        acc[5]  = fmaf(x1, x2, acc[5]);                                    \
        acc[6]  = fmaf(x1, x3, acc[6]);                                    \
        acc[7]  = fmaf(x2, x2, acc[7]);                                    \
        acc[8]  = fmaf(x2, x3, acc[8]);                                    \
        acc[9]  = fmaf(x3, x3, acc[9]);                                    \
        acc[10] = fmaf(x0, y1, acc[10]);                                   \
        acc[11] = fmaf(x1, y1, acc[11]);                                   \
        acc[12] = fmaf(x2, y1, acc[12]);                                   \
        acc[13] = fmaf(x3, y1, acc[13]);                                   \
        acc[14] = fmaf(x0, y2, acc[14]);                                   \
        acc[15] = fmaf(x1, y2, acc[15]);                                   \
        acc[16] = fmaf(x2, y2, acc[16]);                                   \
        acc[17] = fmaf(x3, y2, acc[17]);                                   \
        acc[18] = fmaf(y1, y1, acc[18]);                                   \
        acc[19] = fmaf(y2, y2, acc[19]);                                   \
    } while (0)

        LANE(x); LANE(y); LANE(z); LANE(w);
#undef LANE
    }

    // block reduction of the 20 stats
#pragma unroll
    for (int st = 0; st < NSTAT; st++) {
        float v = acc[st];
        v += __shfl_down_sync(0xffffffffu, v, 16);
        v += __shfl_down_sync(0xffffffffu, v, 8);
        v += __shfl_down_sync(0xffffffffu, v, 4);
        v += __shfl_down_sync(0xffffffffu, v, 2);
        v += __shfl_down_sync(0xffffffffu, v, 1);
        acc[st] = v;
    }
    __shared__ float sred[THREADS / 32][NSTAT];
    const int warp = tid >> 5;
    const int lane = tid & 31;
    if (lane == 0) {
#pragma unroll
        for (int st = 0; st < NSTAT; st++) sred[warp][st] = acc[st];
    }
    __syncthreads();
    if (tid < NSTAT) {
        float s = 0.0f;
#pragma unroll
        for (int w = 0; w < THREADS / 32; w++) s += sred[w][tid];
        g_partials[(b * NSTAT + tid) * CPB + q] = s;
    }

    // ---- last-block epilogue -------------------------------------------
    __shared__ int s_last;
    __threadfence();
    if (tid == 0) {
        int old = atomicAdd(&g_count, 1);
        s_last = (old == NBLOCKS - 1) ? 1 : 0;
    }
    __syncthreads();
    if (!s_last) return;
    __threadfence();

    __shared__ float sstats[NPAIR];
    __shared__ float ksum[NK];

    // 640 pairs / 256 threads: 4 float4 per pair, fixed pairwise order.
    for (int p = tid; p < NPAIR; p += THREADS) {
        const float4* row = (const float4*)(g_partials + p * CPB);
        float4 r0 = row[0], r1 = row[1], r2 = row[2], r3 = row[3];
        sstats[p] = (sum4(r0) + sum4(r1)) + (sum4(r2) + sum4(r3));
    }
    __syncthreads();

    {
        const int w  = tid >> 5;
        const int bb = tid & 31;
        const float* st = &sstats[bb * NSTAT];
        float l0 = mixit_loss(w,     st);
        float l1 = mixit_loss(w + 8, st);
#pragma unroll
        for (int off = 16; off > 0; off >>= 1) {
            l0 += __shfl_down_sync(0xffffffffu, l0, off);
            l1 += __shfl_down_sync(0xffffffffu, l1, off);
        }
        if (bb == 0) { ksum[w] = l0; ksum[w + 8] = l1; }
    }
    __syncthreads();

    if (tid == 0) {
        float best = ksum[0];
        int bi = 0;
#pragma unroll
        for (int kk = 1; kk < NK; kk++) {
            float v = ksum[kk];
            if (v < best) { best = v; bi = kk; }   // first occurrence wins (jnp.argmin)
        }
        out[0] = (float)bi;
        if (out_size > 1) out[1] = best;
        g_count = 0;
    }
}

extern "C" void kernel_launch(void* const* d_in, const int* in_sizes, int n_in,
                              void* d_out, int out_size)
{
    const float* est = (const float*)d_in[0];   // [32, 4, 64000]
    const float* m1  = (const float*)d_in[1];   // [32, 64000]
    const float* m2  = (const float*)d_in[2];   // [32, 64000]

    mixit_kernel<<<NBLOCKS, THREADS>>>(est, m1, m2, (float*)d_out, out_size);
}